// round 9
// baseline (speedup 1.0000x reference)
#include <cuda_runtime.h>
#include <cuda_bf16.h>
#include <math.h>
#include <stdint.h>

#define BATCH 4
#define CH    256
#define HW    4096
#define NSPLIT 64            // 32 i-tiles * 2 m-warps
#define NCHUNK 8             // K chunks of 32 channels
#define STAGEB 49152         // A(16K: hi8|lo8) | B0(16K) | B1(16K)
#define NSTAGE 4
#define SMEM_REQ (NSTAGE*STAGEB + 1024 + 128)
#define NCTA_CO 148
#define TILES_PER_BATCH 512  // 32 it * 16 jt

// staging: per (b, cc, ib128): 16KB block = [hi 8KB | lo 8KB], rows of 64B slot-swizzled
__device__ __nv_bfloat16 g_A[BATCH*NCHUNK*HW*64];    // feat1 (i rows)
__device__ __nv_bfloat16 g_B[BATCH*NCHUNK*HW*64];    // feat2 (j rows)

__device__ float g_pm[NSPLIT*BATCH*HW];
__device__ float g_ps[NSPLIT*BATCH*HW];
__device__ float g_m [BATCH*HW];
__device__ float g_inv[BATCH*HW];
__device__ unsigned g_done [BATCH];   // GEMM tiles completed per batch
__device__ unsigned g_mdone[BATCH];   // merge CTAs completed per batch

// ------------------------------------------------------------------ helpers
static __device__ __forceinline__ uint32_t smem_u32(const void* p){
    uint32_t a;
    asm("{ .reg .u64 t; cvta.to.shared.u64 t, %1; cvt.u32.u64 %0, t; }" : "=r"(a) : "l"(p));
    return a;
}
static __device__ __forceinline__ void mbar_init(uint32_t a, uint32_t c){
    asm volatile("mbarrier.init.shared.b64 [%0], %1;" :: "r"(a), "r"(c) : "memory");
}
static __device__ __forceinline__ void mbar_expect(uint32_t a, uint32_t tx){
    asm volatile("mbarrier.arrive.expect_tx.shared.b64 _, [%0], %1;" :: "r"(a), "r"(tx) : "memory");
}
static __device__ __forceinline__ void mbar_arrive(uint32_t a){
    asm volatile("mbarrier.arrive.shared.b64 _, [%0];" :: "r"(a) : "memory");
}
static __device__ __forceinline__ void mbar_wait(uint32_t a, uint32_t par){
    asm volatile("{\n\t.reg .pred P;\n\t"
                 "WL_%=:\n\t"
                 "mbarrier.try_wait.parity.acquire.cta.shared::cta.b64 P, [%0], %1, 0x989680;\n\t"
                 "@P bra WD_%=;\n\t"
                 "bra WL_%=;\n\t"
                 "WD_%=:\n\t}" :: "r"(a), "r"(par) : "memory");
}
static __device__ __forceinline__ void bulk_g2s(uint32_t dst, const void* src,
                                                uint32_t bytes, uint32_t mbar){
    asm volatile("cp.async.bulk.shared::cluster.global.mbarrier::complete_tx::bytes "
                 "[%0], [%1], %2, [%3];"
                 :: "r"(dst), "l"(src), "r"(bytes), "r"(mbar) : "memory");
}
static __device__ __forceinline__ void red_release_add(unsigned* p, unsigned v){
    asm volatile("red.release.gpu.global.add.u32 [%0], %1;" :: "l"(p), "r"(v) : "memory");
}
static __device__ __forceinline__ unsigned ld_acquire(const unsigned* p){
    unsigned v;
    asm volatile("ld.acquire.gpu.global.u32 %0, [%1];" : "=r"(v) : "l"(p) : "memory");
    return v;
}

#define LDSM4(r, addr) \
    asm volatile("ldmatrix.sync.aligned.m8n8.x4.shared.b16 {%0,%1,%2,%3}, [%4];" \
        : "=r"((r)[0]), "=r"((r)[1]), "=r"((r)[2]), "=r"((r)[3]) : "r"(addr))

#define MMA(d, a, bb) \
    asm volatile("mma.sync.aligned.m16n8k16.row.col.f32.bf16.bf16.f32 " \
        "{%0,%1,%2,%3},{%4,%5,%6,%7},{%8,%9},{%0,%1,%2,%3};" \
        : "+f"((d)[0]), "+f"((d)[1]), "+f"((d)[2]), "+f"((d)[3]) \
        : "r"((a)[0]), "r"((a)[1]), "r"((a)[2]), "r"((a)[3]), "r"((bb)[0]), "r"((bb)[1]))

// ------------------------------------------------------------------ pre-pass
__global__ __launch_bounds__(256) void split_prep(const float* __restrict__ f1,
                                                  const float* __restrict__ f2)
{
    __shared__ float s[32][129];
    const int bid = blockIdx.x;
    if (bid == 0 && threadIdx.x < 2 * BATCH) {      // reset progress counters
        if (threadIdx.x < BATCH) g_done[threadIdx.x] = 0;
        else                     g_mdone[threadIdx.x - BATCH] = 0;
    }
    const int ib  = bid & 31;
    const int cc  = (bid >> 5) & 7;
    const int b   = (bid >> 8) & 3;
    const int arr = bid >> 10;
    const float* in = arr ? f2 : f1;
    __nv_bfloat16* o = arr ? g_B : g_A;
    const int t = threadIdx.x;

#pragma unroll
    for (int k = 0; k < 4; k++) {
        const int lin = k * 256 + t;
        const int c   = lin >> 5;
        const int x4  = lin & 31;
        const float4 v = *(const float4*)(in + ((size_t)(b*CH + cc*32 + c))*HW + ib*128 + x4*4);
        s[c][x4*4+0] = v.x; s[c][x4*4+1] = v.y; s[c][x4*4+2] = v.z; s[c][x4*4+3] = v.w;
    }
    __syncthreads();

    const int slot = t & 3;
    const size_t blk = (((size_t)(b*NCHUNK + cc))*32 + ib) * 16384;
#pragma unroll
    for (int rr = 0; rr < 2; rr++) {
        const int row = rr * 64 + (t >> 2);
        const uint32_t byte = (uint32_t)(row * 64) +
                              ((uint32_t)(slot << 4) ^ (uint32_t)(((row >> 1) & 3) << 4));
        uint32_t hp[4], lp[4];
#pragma unroll
        for (int u = 0; u < 4; u++) {
            const int c = slot*8 + u*2;
            const float v0 = s[c][row], v1 = s[c+1][row];
            const __nv_bfloat16 h0 = __float2bfloat16(v0);
            const __nv_bfloat16 h1 = __float2bfloat16(v1);
            const __nv_bfloat16 l0 = __float2bfloat16(v0 - __bfloat162float(h0));
            const __nv_bfloat16 l1 = __float2bfloat16(v1 - __bfloat162float(h1));
            hp[u] = ((uint32_t)__bfloat16_as_ushort(h1) << 16) | __bfloat16_as_ushort(h0);
            lp[u] = ((uint32_t)__bfloat16_as_ushort(l1) << 16) | __bfloat16_as_ushort(l0);
        }
        *(uint4*)((char*)o + blk        + byte) = make_uint4(hp[0], hp[1], hp[2], hp[3]);
        *(uint4*)((char*)o + blk + 8192 + byte) = make_uint4(lp[0], lp[1], lp[2], lp[3]);
    }
}

// ------------------------------------------------------------------ GEMM
// C[i,j] tile 128x256, 256 threads, bf16-3x, 4-stage pipeline, fused softmax
// partials, per-batch completion signaling (release) for the co-kernel.
__global__ __launch_bounds__(256, 1) void corr_mma(float* __restrict__ out)
{
    extern __shared__ char dsm[];
    uint32_t base = smem_u32(dsm);
    base = (base + 1023) & ~1023u;
    const uint32_t mbF = base + NSTAGE * STAGEB;
    const uint32_t mbE = mbF + 32;

    const int tid  = threadIdx.x;
    const int lane = tid & 31;
    const int wid  = tid >> 5;
    const int wm   = wid >> 2;
    const int wn   = wid & 3;
    const int jt = blockIdx.x, it = blockIdx.y, b = blockIdx.z;

    if (tid == 0) {
#pragma unroll
        for (int s = 0; s < NSTAGE; s++) { mbar_init(mbF + 8*s, 1); mbar_init(mbE + 8*s, 8); }
        asm volatile("fence.proxy.async.shared::cta;" ::: "memory");
    }
    __syncthreads();

    #define ISSUE(c, s) do { \
        const size_t offA = (((size_t)(b*NCHUNK + (c)))*32 + it)   * 16384; \
        const size_t offB = (((size_t)(b*NCHUNK + (c)))*32 + jt*2) * 16384; \
        mbar_expect(mbF + 8*(s), STAGEB); \
        bulk_g2s(base + (s)*STAGEB +     0, (const char*)g_A + offA,         16384, mbF + 8*(s)); \
        bulk_g2s(base + (s)*STAGEB + 16384, (const char*)g_B + offB,         16384, mbF + 8*(s)); \
        bulk_g2s(base + (s)*STAGEB + 32768, (const char*)g_B + offB + 16384, 16384, mbF + 8*(s)); \
    } while (0)

    if (tid == 0) { ISSUE(0,0); ISSUE(1,1); ISSUE(2,2); ISSUE(3,3); }

    float acc[4][8][4];
#pragma unroll
    for (int mt = 0; mt < 4; mt++)
#pragma unroll
        for (int nt = 0; nt < 8; nt++)
#pragma unroll
            for (int e = 0; e < 4; e++) acc[mt][nt][e] = 0.f;

    const int rA  = lane & 15;
    const int khA = (lane & 16) ? 16 : 0;
    const int rB  = (lane & 7) + ((lane & 16) ? 8 : 0);
    const int khB = (lane & 8)  ? 16 : 0;
    const uint32_t swA = (uint32_t)(((rA >> 1) & 3) << 4);
    const uint32_t swB = (uint32_t)(((rB >> 1) & 3) << 4);
    const uint32_t rowAoff = (uint32_t)((wm*64 + rA) * 64);
    const int rowBg = wn*64 + rB;
    const uint32_t rowBoff = (uint32_t)(16384 + (rowBg >> 7) * 16384 + (rowBg & 127) * 64);

    for (int c = 0; c < NCHUNK; c++) {
        const int s = c & 3;
        const uint32_t par = (uint32_t)((c >> 2) & 1);
        mbar_wait(mbF + 8*s, par);

        const uint32_t aAh = base + s*STAGEB + rowAoff;
        const uint32_t aAl = aAh + 8192;
        const uint32_t aBh = base + s*STAGEB + rowBoff;
        const uint32_t aBl = aBh + 8192;

#pragma unroll
        for (int kk = 0; kk < 2; kk++) {
            const uint32_t colA = ((uint32_t)(kk*32 + khA)) ^ swA;
            const uint32_t colB = ((uint32_t)(kk*32 + khB)) ^ swB;
            uint32_t ah[4][4], al[4][4], bh[4][4], bl[4][4];
#pragma unroll
            for (int mt = 0; mt < 4; mt++) {
                LDSM4(ah[mt], aAh + mt*1024 + colA);
                LDSM4(al[mt], aAl + mt*1024 + colA);
            }
#pragma unroll
            for (int np = 0; np < 4; np++) {
                LDSM4(bh[np], aBh + np*1024 + colB);
                LDSM4(bl[np], aBl + np*1024 + colB);
            }
#pragma unroll
            for (int mt = 0; mt < 4; mt++)
#pragma unroll
                for (int nt = 0; nt < 8; nt++)
                    MMA(acc[mt][nt], ah[mt], (&bh[nt >> 1][(nt & 1) * 2]));
#pragma unroll
            for (int mt = 0; mt < 4; mt++)
#pragma unroll
                for (int nt = 0; nt < 8; nt++)
                    MMA(acc[mt][nt], ah[mt], (&bl[nt >> 1][(nt & 1) * 2]));
#pragma unroll
            for (int mt = 0; mt < 4; mt++)
#pragma unroll
                for (int nt = 0; nt < 8; nt++)
                    MMA(acc[mt][nt], al[mt], (&bh[nt >> 1][(nt & 1) * 2]));
        }
        if (c < NCHUNK - NSTAGE) {
            __syncwarp();
            if (lane == 0) mbar_arrive(mbE + 8*s);
            if (tid == 0) { mbar_wait(mbE + 8*s, par); ISSUE(c + NSTAGE, s); }
        }
    }

    // ---------------- epilogue: store C + fused per-column softmax partials
    const int g   = lane >> 2;
    const int tig = lane & 3;
    float* outb = out + (size_t)b*HW*HW + (size_t)(it*128)*HW + jt*256;

#pragma unroll
    for (int mt = 0; mt < 4; mt++)
#pragma unroll
        for (int nt = 0; nt < 8; nt++) {
            const int r0 = wm*64 + mt*16 + g;
            const int cc = wn*64 + nt*8 + tig*2;
            *(float2*)(outb + (size_t)r0     * HW + cc) = make_float2(acc[mt][nt][0], acc[mt][nt][1]);
            *(float2*)(outb + (size_t)(r0+8) * HW + cc) = make_float2(acc[mt][nt][2], acc[mt][nt][3]);
        }

    float cm[8][2], cs[8][2];
#pragma unroll
    for (int nt = 0; nt < 8; nt++)
#pragma unroll
        for (int e = 0; e < 2; e++) {
            float m = -INFINITY;
#pragma unroll
            for (int mt = 0; mt < 4; mt++) {
                m = fmaxf(m, acc[mt][nt][e]);
                m = fmaxf(m, acc[mt][nt][2 + e]);
            }
            cm[nt][e] = m;
        }
#pragma unroll
    for (int d = 4; d <= 16; d <<= 1)
#pragma unroll
        for (int nt = 0; nt < 8; nt++)
#pragma unroll
            for (int e = 0; e < 2; e++)
                cm[nt][e] = fmaxf(cm[nt][e], __shfl_xor_sync(0xffffffffu, cm[nt][e], d));

#pragma unroll
    for (int nt = 0; nt < 8; nt++)
#pragma unroll
        for (int e = 0; e < 2; e++) {
            float ssum = 0.f;
#pragma unroll
            for (int mt = 0; mt < 4; mt++) {
                ssum += __expf(acc[mt][nt][e]     - cm[nt][e]);
                ssum += __expf(acc[mt][nt][2 + e] - cm[nt][e]);
            }
            cs[nt][e] = ssum;
        }
#pragma unroll
    for (int d = 4; d <= 16; d <<= 1)
#pragma unroll
        for (int nt = 0; nt < 8; nt++)
#pragma unroll
            for (int e = 0; e < 2; e++)
                cs[nt][e] += __shfl_xor_sync(0xffffffffu, cs[nt][e], d);

    if (lane < 4) {
        const int split = it*2 + wm;
#pragma unroll
        for (int nt = 0; nt < 8; nt++)
#pragma unroll
            for (int e = 0; e < 2; e++) {
                const int jg = jt*256 + wn*64 + nt*8 + lane*2 + e;
                const size_t po = ((size_t)split*BATCH + b)*HW + jg;
                g_pm[po] = cm[nt][e];
                g_ps[po] = cs[nt][e];
            }
    }

    // signal tile completion for this batch (release: prior stores visible)
    __syncthreads();
    if (tid == 0) red_release_add(&g_done[b], 1u);
}

// ------------------------------------------------------------------ co-kernel
// 148 co-resident CTAs: for batches 0..2, wait for the GEMM to finish the
// batch, then merge stats (CTAs 0-15) and finalize (all CTAs, grid-stride) —
// overlapped with the GEMM's remaining batches.
__global__ __launch_bounds__(256) void softmax_co(float* __restrict__ out)
{
    const int tid = threadIdx.x;
    const int cta = blockIdx.x;

    for (int b = 0; b < 3; b++) {
        if (tid == 0) {
            while (ld_acquire(&g_done[b]) < TILES_PER_BATCH) __nanosleep(256);
        }
        __syncthreads();

        if (cta < 16) {                       // merge: 16 CTAs x 256 = 4096 j
            const int idx = b * HW + cta * 256 + tid;
            float m = -INFINITY;
#pragma unroll 8
            for (int s = 0; s < NSPLIT; s++)
                m = fmaxf(m, g_pm[(size_t)s * BATCH * HW + idx]);
            float sum = 0.f;
#pragma unroll 8
            for (int s = 0; s < NSPLIT; s++)
                sum += g_ps[(size_t)s * BATCH * HW + idx] *
                       __expf(g_pm[(size_t)s * BATCH * HW + idx] - m);
            g_m[idx]   = m;
            g_inv[idx] = 1.f / sum;
            __syncthreads();
            if (tid == 0) red_release_add(&g_mdone[b], 1u);
        }
        if (tid == 0) {
            while (ld_acquire(&g_mdone[b]) < 16u) __nanosleep(128);
        }
        __syncthreads();

        // finalize this batch, grid-stride over float4 elements
        const size_t per    = (size_t)HW * HW / 4;       // 4.19M float4
        const size_t stride = (size_t)NCTA_CO * 256;
        const float* mrow = g_m   + (size_t)b * HW;
        const float* vrow = g_inv + (size_t)b * HW;
        float* ob = out + (size_t)b * HW * HW;
#pragma unroll 2
        for (size_t q = (size_t)cta * 256 + tid; q < per; q += stride) {
            const size_t e = q * 4;
            const int j = (int)(e & (HW - 1));
            float4 x = *(float4*)(ob + e);
            const float4 m4 = *(const float4*)(mrow + j);
            const float4 v4 = *(const float4*)(vrow + j);
            x.x = __expf(x.x - m4.x) * v4.x;
            x.y = __expf(x.y - m4.y) * v4.y;
            x.z = __expf(x.z - m4.z) * v4.z;
            x.w = __expf(x.w - m4.w) * v4.w;
            *(float4*)(ob + e) = x;
        }
    }
}

// ------------------------------------------------------------------ batch-3 tail
__global__ __launch_bounds__(256) void merge_stats_b(int b)
{
    const int idx = b * HW + blockIdx.x * 256 + threadIdx.x;
    float m = -INFINITY;
#pragma unroll 8
    for (int s = 0; s < NSPLIT; s++)
        m = fmaxf(m, g_pm[(size_t)s * BATCH * HW + idx]);
    float sum = 0.f;
#pragma unroll 8
    for (int s = 0; s < NSPLIT; s++)
        sum += g_ps[(size_t)s * BATCH * HW + idx] *
               __expf(g_pm[(size_t)s * BATCH * HW + idx] - m);
    g_m[idx]   = m;
    g_inv[idx] = 1.f / sum;
}

__global__ __launch_bounds__(256) void finalize_b(float* __restrict__ out, int b)
{
    const size_t q = (size_t)b * HW * HW +
                     ((size_t)blockIdx.x * 256 + threadIdx.x) * 4;
    const int j = (int)(q & (HW - 1));

    float4 x = *(float4*)(out + q);
    const float4 m4 = *(const float4*)(g_m   + (size_t)b * HW + j);
    const float4 v4 = *(const float4*)(g_inv + (size_t)b * HW + j);
    x.x = __expf(x.x - m4.x) * v4.x;
    x.y = __expf(x.y - m4.y) * v4.y;
    x.z = __expf(x.z - m4.z) * v4.z;
    x.w = __expf(x.w - m4.w) * v4.w;
    *(float4*)(out + q) = x;
}

// ------------------------------------------------------------------
extern "C" void kernel_launch(void* const* d_in, const int* in_sizes, int n_in,
                              void* d_out, int out_size)
{
    const float* f1 = (const float*)d_in[0];
    const float* f2 = (const float*)d_in[1];
    float* out = (float*)d_out;

    static cudaStream_t s2 = nullptr;
    static cudaEvent_t evF, evJ;
    if (s2 == nullptr) {
        cudaStreamCreateWithFlags(&s2, cudaStreamNonBlocking);
        cudaEventCreateWithFlags(&evF, cudaEventDisableTiming);
        cudaEventCreateWithFlags(&evJ, cudaEventDisableTiming);
        cudaFuncSetAttribute(corr_mma, cudaFuncAttributeMaxDynamicSharedMemorySize, SMEM_REQ);
    }

    split_prep<<<2048, 256>>>(f1, f2);

    // fork: co-kernel (batches 0-2 softmax) runs concurrently with the GEMM
    cudaEventRecord(evF, 0);
    cudaStreamWaitEvent(s2, evF, 0);
    softmax_co<<<NCTA_CO, 256, 0, s2>>>(out);
    cudaEventRecord(evJ, s2);

    dim3 g(HW / 256, HW / 128, BATCH);           // 16 x 32 x 4
    corr_mma<<<g, 256, SMEM_REQ>>>(out);

    // batch 3 tail at full width on the main stream
    merge_stats_b<<<HW / 256, 256>>>(3);
    finalize_b<<<(unsigned)((size_t)HW * HW / 4 / 256), 256>>>(out, 3);

    cudaStreamWaitEvent(0, evJ, 0);
}

// round 10
// speedup vs baseline: 20.9729x; 20.9729x over previous
#include <cuda_runtime.h>
#include <cuda_bf16.h>
#include <math.h>
#include <stdint.h>

#define BATCH 4
#define CH    256
#define HW    4096
#define NSPLIT 64            // 32 i-tiles * 2 m-warps
#define NCHUNK 8             // K chunks of 32 channels
#define STAGEB 32768         // A(16K: hi8|lo8) | B(16K: hi8|lo8)
#define NSTAGE 3
#define SMEM_REQ (NSTAGE*STAGEB + 1024 + 128)

// staging: per (b, cc, ib128): 16KB block = [hi 8KB | lo 8KB], rows of 64B slot-swizzled
__device__ __nv_bfloat16 g_A[BATCH*NCHUNK*HW*64];    // feat1 (i rows)
__device__ __nv_bfloat16 g_B[BATCH*NCHUNK*HW*64];    // feat2 (j rows)

__device__ float g_pm[NSPLIT*BATCH*HW];
__device__ float g_ps[NSPLIT*BATCH*HW];
__device__ float g_m [BATCH*HW];
__device__ float g_inv[BATCH*HW];

// ------------------------------------------------------------------ helpers
static __device__ __forceinline__ uint32_t smem_u32(const void* p){
    uint32_t a;
    asm("{ .reg .u64 t; cvta.to.shared.u64 t, %1; cvt.u32.u64 %0, t; }" : "=r"(a) : "l"(p));
    return a;
}
static __device__ __forceinline__ void mbar_init(uint32_t a, uint32_t c){
    asm volatile("mbarrier.init.shared.b64 [%0], %1;" :: "r"(a), "r"(c) : "memory");
}
static __device__ __forceinline__ void mbar_expect(uint32_t a, uint32_t tx){
    asm volatile("mbarrier.arrive.expect_tx.shared.b64 _, [%0], %1;" :: "r"(a), "r"(tx) : "memory");
}
static __device__ __forceinline__ void mbar_arrive(uint32_t a){
    asm volatile("mbarrier.arrive.shared.b64 _, [%0];" :: "r"(a) : "memory");
}
static __device__ __forceinline__ void mbar_wait(uint32_t a, uint32_t par){
    asm volatile("{\n\t.reg .pred P;\n\t"
                 "WL_%=:\n\t"
                 "mbarrier.try_wait.parity.acquire.cta.shared::cta.b64 P, [%0], %1, 0x989680;\n\t"
                 "@P bra WD_%=;\n\t"
                 "bra WL_%=;\n\t"
                 "WD_%=:\n\t}" :: "r"(a), "r"(par) : "memory");
}
static __device__ __forceinline__ void bulk_g2s(uint32_t dst, const void* src,
                                                uint32_t bytes, uint32_t mbar){
    asm volatile("cp.async.bulk.shared::cluster.global.mbarrier::complete_tx::bytes "
                 "[%0], [%1], %2, [%3];"
                 :: "r"(dst), "l"(src), "r"(bytes), "r"(mbar) : "memory");
}

#define LDSM4(r, addr) \
    asm volatile("ldmatrix.sync.aligned.m8n8.x4.shared.b16 {%0,%1,%2,%3}, [%4];" \
        : "=r"((r)[0]), "=r"((r)[1]), "=r"((r)[2]), "=r"((r)[3]) : "r"(addr))

#define MMA(d, a, bb) \
    asm volatile("mma.sync.aligned.m16n8k16.row.col.f32.bf16.bf16.f32 " \
        "{%0,%1,%2,%3},{%4,%5,%6,%7},{%8,%9},{%0,%1,%2,%3};" \
        : "+f"((d)[0]), "+f"((d)[1]), "+f"((d)[2]), "+f"((d)[3]) \
        : "r"((a)[0]), "r"((a)[1]), "r"((a)[2]), "r"((a)[3]), "r"((bb)[0]), "r"((bb)[1]))

// ------------------------------------------------------------------ pre-pass
__global__ __launch_bounds__(256) void split_prep(const float* __restrict__ f1,
                                                  const float* __restrict__ f2)
{
    __shared__ float s[32][129];
    const int bid = blockIdx.x;
    const int ib  = bid & 31;
    const int cc  = (bid >> 5) & 7;
    const int b   = (bid >> 8) & 3;
    const int arr = bid >> 10;
    const float* in = arr ? f2 : f1;
    __nv_bfloat16* o = arr ? g_B : g_A;
    const int t = threadIdx.x;

#pragma unroll
    for (int k = 0; k < 4; k++) {
        const int lin = k * 256 + t;
        const int c   = lin >> 5;
        const int x4  = lin & 31;
        const float4 v = *(const float4*)(in + ((size_t)(b*CH + cc*32 + c))*HW + ib*128 + x4*4);
        s[c][x4*4+0] = v.x; s[c][x4*4+1] = v.y; s[c][x4*4+2] = v.z; s[c][x4*4+3] = v.w;
    }
    __syncthreads();

    const int slot = t & 3;
    const size_t blk = (((size_t)(b*NCHUNK + cc))*32 + ib) * 16384;
#pragma unroll
    for (int rr = 0; rr < 2; rr++) {
        const int row = rr * 64 + (t >> 2);
        const uint32_t byte = (uint32_t)(row * 64) +
                              ((uint32_t)(slot << 4) ^ (uint32_t)(((row >> 1) & 3) << 4));
        uint32_t hp[4], lp[4];
#pragma unroll
        for (int u = 0; u < 4; u++) {
            const int c = slot*8 + u*2;
            const float v0 = s[c][row], v1 = s[c+1][row];
            const __nv_bfloat16 h0 = __float2bfloat16(v0);
            const __nv_bfloat16 h1 = __float2bfloat16(v1);
            const __nv_bfloat16 l0 = __float2bfloat16(v0 - __bfloat162float(h0));
            const __nv_bfloat16 l1 = __float2bfloat16(v1 - __bfloat162float(h1));
            hp[u] = ((uint32_t)__bfloat16_as_ushort(h1) << 16) | __bfloat16_as_ushort(h0);
            lp[u] = ((uint32_t)__bfloat16_as_ushort(l1) << 16) | __bfloat16_as_ushort(l0);
        }
        *(uint4*)((char*)o + blk        + byte) = make_uint4(hp[0], hp[1], hp[2], hp[3]);
        *(uint4*)((char*)o + blk + 8192 + byte) = make_uint4(lp[0], lp[1], lp[2], lp[3]);
    }
}

// ------------------------------------------------------------------ GEMM
// C[i,j] tile 128x128, 128 threads (2x2 warps, 64x64 warp tiles), bf16-3x,
// 3-stage pipeline, 2 CTAs/SM so epilogue overlaps the co-resident CTA's MMAs.
__global__ __launch_bounds__(128, 2) void corr_mma(float* __restrict__ out)
{
    extern __shared__ char dsm[];
    uint32_t base = smem_u32(dsm);
    base = (base + 1023) & ~1023u;
    const uint32_t mbF = base + NSTAGE * STAGEB;       // full[3]
    const uint32_t mbE = mbF + 24;                     // empty[3]

    const int tid  = threadIdx.x;
    const int lane = tid & 31;
    const int wid  = tid >> 5;     // 0..3
    const int wm   = wid >> 1;     // 0..1
    const int wn   = wid & 1;      // 0..1
    const int jt = blockIdx.x, it = blockIdx.y, b = blockIdx.z;

    if (tid == 0) {
#pragma unroll
        for (int s = 0; s < NSTAGE; s++) { mbar_init(mbF + 8*s, 1); mbar_init(mbE + 8*s, 4); }
        asm volatile("fence.proxy.async.shared::cta;" ::: "memory");
    }
    __syncthreads();

    #define ISSUE(c, s) do { \
        const size_t offA = (((size_t)(b*NCHUNK + (c)))*32 + it) * 16384; \
        const size_t offB = (((size_t)(b*NCHUNK + (c)))*32 + jt) * 16384; \
        mbar_expect(mbF + 8*(s), STAGEB); \
        bulk_g2s(base + (s)*STAGEB +     0, (const char*)g_A + offA, 16384, mbF + 8*(s)); \
        bulk_g2s(base + (s)*STAGEB + 16384, (const char*)g_B + offB, 16384, mbF + 8*(s)); \
    } while (0)

    if (tid == 0) { ISSUE(0,0); ISSUE(1,1); ISSUE(2,2); }

    float acc[4][8][4];
#pragma unroll
    for (int mt = 0; mt < 4; mt++)
#pragma unroll
        for (int nt = 0; nt < 8; nt++)
#pragma unroll
            for (int e = 0; e < 4; e++) acc[mt][nt][e] = 0.f;

    const int rA  = lane & 15;
    const int khA = (lane & 16) ? 16 : 0;
    const int rB  = (lane & 7) + ((lane & 16) ? 8 : 0);
    const int khB = (lane & 8)  ? 16 : 0;
    const uint32_t swA = (uint32_t)(((rA >> 1) & 3) << 4);
    const uint32_t swB = (uint32_t)(((rB >> 1) & 3) << 4);
    const uint32_t rowAoff = (uint32_t)((wm*64 + rA) * 64);
    const uint32_t rowBoff = (uint32_t)(16384 + (wn*64 + rB) * 64);

    for (int c = 0; c < NCHUNK; c++) {
        const int s = c % NSTAGE;
        const uint32_t par = (uint32_t)((c / NSTAGE) & 1);
        mbar_wait(mbF + 8*s, par);

        const uint32_t aAh = base + s*STAGEB + rowAoff;
        const uint32_t aAl = aAh + 8192;
        const uint32_t aBh = base + s*STAGEB + rowBoff;
        const uint32_t aBl = aBh + 8192;

#pragma unroll
        for (int kk = 0; kk < 2; kk++) {
            const uint32_t colA = ((uint32_t)(kk*32 + khA)) ^ swA;
            const uint32_t colB = ((uint32_t)(kk*32 + khB)) ^ swB;
            uint32_t ah[4][4], al[4][4], bh[4][4], bl[4][4];
#pragma unroll
            for (int mt = 0; mt < 4; mt++) {
                LDSM4(ah[mt], aAh + mt*1024 + colA);
                LDSM4(al[mt], aAl + mt*1024 + colA);
            }
#pragma unroll
            for (int np = 0; np < 4; np++) {
                LDSM4(bh[np], aBh + np*1024 + colB);
                LDSM4(bl[np], aBl + np*1024 + colB);
            }
#pragma unroll
            for (int mt = 0; mt < 4; mt++)
#pragma unroll
                for (int nt = 0; nt < 8; nt++)
                    MMA(acc[mt][nt], ah[mt], (&bh[nt >> 1][(nt & 1) * 2]));
#pragma unroll
            for (int mt = 0; mt < 4; mt++)
#pragma unroll
                for (int nt = 0; nt < 8; nt++)
                    MMA(acc[mt][nt], ah[mt], (&bl[nt >> 1][(nt & 1) * 2]));
#pragma unroll
            for (int mt = 0; mt < 4; mt++)
#pragma unroll
                for (int nt = 0; nt < 8; nt++)
                    MMA(acc[mt][nt], al[mt], (&bh[nt >> 1][(nt & 1) * 2]));
        }
        if (c < NCHUNK - NSTAGE) {
            __syncwarp();
            if (lane == 0) mbar_arrive(mbE + 8*s);
            if (tid == 0) { mbar_wait(mbE + 8*s, par); ISSUE(c + NSTAGE, s); }
        }
    }

    // ---------------- epilogue: store C + fused per-column softmax partials
    const int g   = lane >> 2;
    const int tig = lane & 3;
    float* outb = out + (size_t)b*HW*HW + (size_t)(it*128)*HW + jt*128;

#pragma unroll
    for (int mt = 0; mt < 4; mt++)
#pragma unroll
        for (int nt = 0; nt < 8; nt++) {
            const int r0 = wm*64 + mt*16 + g;
            const int cc = wn*64 + nt*8 + tig*2;
            *(float2*)(outb + (size_t)r0     * HW + cc) = make_float2(acc[mt][nt][0], acc[mt][nt][1]);
            *(float2*)(outb + (size_t)(r0+8) * HW + cc) = make_float2(acc[mt][nt][2], acc[mt][nt][3]);
        }

    float cm[8][2], cs[8][2];
#pragma unroll
    for (int nt = 0; nt < 8; nt++)
#pragma unroll
        for (int e = 0; e < 2; e++) {
            float m = -INFINITY;
#pragma unroll
            for (int mt = 0; mt < 4; mt++) {
                m = fmaxf(m, acc[mt][nt][e]);
                m = fmaxf(m, acc[mt][nt][2 + e]);
            }
            cm[nt][e] = m;
        }
#pragma unroll
    for (int d = 4; d <= 16; d <<= 1)
#pragma unroll
        for (int nt = 0; nt < 8; nt++)
#pragma unroll
            for (int e = 0; e < 2; e++)
                cm[nt][e] = fmaxf(cm[nt][e], __shfl_xor_sync(0xffffffffu, cm[nt][e], d));

#pragma unroll
    for (int nt = 0; nt < 8; nt++)
#pragma unroll
        for (int e = 0; e < 2; e++) {
            float ssum = 0.f;
#pragma unroll
            for (int mt = 0; mt < 4; mt++) {
                ssum += __expf(acc[mt][nt][e]     - cm[nt][e]);
                ssum += __expf(acc[mt][nt][2 + e] - cm[nt][e]);
            }
            cs[nt][e] = ssum;
        }
#pragma unroll
    for (int d = 4; d <= 16; d <<= 1)
#pragma unroll
        for (int nt = 0; nt < 8; nt++)
#pragma unroll
            for (int e = 0; e < 2; e++)
                cs[nt][e] += __shfl_xor_sync(0xffffffffu, cs[nt][e], d);

    if (lane < 4) {
        const int split = it*2 + wm;
#pragma unroll
        for (int nt = 0; nt < 8; nt++)
#pragma unroll
            for (int e = 0; e < 2; e++) {
                const int jg = jt*128 + wn*64 + nt*8 + lane*2 + e;
                const size_t po = ((size_t)split*BATCH + b)*HW + jg;
                g_pm[po] = cm[nt][e];
                g_ps[po] = cs[nt][e];
            }
    }
}

// ------------------------------------------------------------------ merge
__global__ __launch_bounds__(256) void merge_stats()
{
    const int idx = blockIdx.x * 256 + threadIdx.x;
    float m = -INFINITY;
#pragma unroll 8
    for (int s = 0; s < NSPLIT; s++)
        m = fmaxf(m, g_pm[(size_t)s * BATCH * HW + idx]);
    float sum = 0.f;
#pragma unroll 8
    for (int s = 0; s < NSPLIT; s++)
        sum += g_ps[(size_t)s * BATCH * HW + idx] *
               __expf(g_pm[(size_t)s * BATCH * HW + idx] - m);
    g_m[idx]   = m;
    g_inv[idx] = 1.f / sum;
}

// ------------------------------------------------------------------ finalize
__global__ __launch_bounds__(256) void finalize(float* __restrict__ out)
{
    const size_t q = ((size_t)blockIdx.x * 256 + threadIdx.x) * 4;
    const int j = (int)(q & (HW - 1));
    const int b = (int)(q >> 24);

    float4 x = *(float4*)(out + q);
    const float4 m4 = *(const float4*)(g_m   + (size_t)b * HW + j);
    const float4 v4 = *(const float4*)(g_inv + (size_t)b * HW + j);
    x.x = __expf(x.x - m4.x) * v4.x;
    x.y = __expf(x.y - m4.y) * v4.y;
    x.z = __expf(x.z - m4.z) * v4.z;
    x.w = __expf(x.w - m4.w) * v4.w;
    *(float4*)(out + q) = x;
}

// ------------------------------------------------------------------
extern "C" void kernel_launch(void* const* d_in, const int* in_sizes, int n_in,
                              void* d_out, int out_size)
{
    const float* f1 = (const float*)d_in[0];
    const float* f2 = (const float*)d_in[1];
    float* out = (float*)d_out;

    static bool smem_set = false;
    if (!smem_set) {
        cudaFuncSetAttribute(corr_mma, cudaFuncAttributeMaxDynamicSharedMemorySize, SMEM_REQ);
        smem_set = true;
    }

    split_prep<<<2048, 256>>>(f1, f2);

    dim3 g(HW / 128, HW / 128, BATCH);           // 32 x 32 x 4
    corr_mma<<<g, 128, SMEM_REQ>>>(out);

    merge_stats<<<(BATCH * HW) / 256, 256>>>();

    const size_t total = (size_t)BATCH * HW * HW;
    finalize<<<(unsigned)(total / 4 / 256), 256>>>(out);
}

// round 11
// speedup vs baseline: 21.9960x; 1.0488x over previous
#include <cuda_runtime.h>
#include <cuda_bf16.h>
#include <cuda_fp16.h>
#include <math.h>
#include <stdint.h>

#define BATCH 4
#define CH    256
#define HW    4096
#define NSPLIT 64            // 32 i-tiles * 2 m-warps (split = i >> 6)
#define NCHUNK 8             // K chunks of 32 channels
#define STAGEB 32768         // A(16K: hi8|lo8) | B(16K: hi8|lo8)
#define NSTAGE 3
#define SMEM_REQ (NSTAGE*STAGEB + 1024 + 128)

// staging: per (b, cc, ib128): 16KB block = [hi 8KB | lo 8KB], rows of 64B slot-swizzled
__device__ __nv_bfloat16 g_A[BATCH*NCHUNK*HW*64];    // feat1 (i rows)
__device__ __nv_bfloat16 g_B[BATCH*NCHUNK*HW*64];    // feat2 (j rows)

__device__ __half g_e[(size_t)BATCH*HW*HW];          // exp(x - m_split), fp16
__device__ float g_pm[NSPLIT*BATCH*HW];
__device__ float g_ps[NSPLIT*BATCH*HW];
__device__ float g_sc[NSPLIT*BATCH*HW];              // exp(m_split-m)*inv

// ------------------------------------------------------------------ helpers
static __device__ __forceinline__ uint32_t smem_u32(const void* p){
    uint32_t a;
    asm("{ .reg .u64 t; cvta.to.shared.u64 t, %1; cvt.u32.u64 %0, t; }" : "=r"(a) : "l"(p));
    return a;
}
static __device__ __forceinline__ void mbar_init(uint32_t a, uint32_t c){
    asm volatile("mbarrier.init.shared.b64 [%0], %1;" :: "r"(a), "r"(c) : "memory");
}
static __device__ __forceinline__ void mbar_expect(uint32_t a, uint32_t tx){
    asm volatile("mbarrier.arrive.expect_tx.shared.b64 _, [%0], %1;" :: "r"(a), "r"(tx) : "memory");
}
static __device__ __forceinline__ void mbar_arrive(uint32_t a){
    asm volatile("mbarrier.arrive.shared.b64 _, [%0];" :: "r"(a) : "memory");
}
static __device__ __forceinline__ void mbar_wait(uint32_t a, uint32_t par){
    asm volatile("{\n\t.reg .pred P;\n\t"
                 "WL_%=:\n\t"
                 "mbarrier.try_wait.parity.acquire.cta.shared::cta.b64 P, [%0], %1, 0x989680;\n\t"
                 "@P bra WD_%=;\n\t"
                 "bra WL_%=;\n\t"
                 "WD_%=:\n\t}" :: "r"(a), "r"(par) : "memory");
}
static __device__ __forceinline__ void bulk_g2s(uint32_t dst, const void* src,
                                                uint32_t bytes, uint32_t mbar){
    asm volatile("cp.async.bulk.shared::cluster.global.mbarrier::complete_tx::bytes "
                 "[%0], [%1], %2, [%3];"
                 :: "r"(dst), "l"(src), "r"(bytes), "r"(mbar) : "memory");
}

#define LDSM4(r, addr) \
    asm volatile("ldmatrix.sync.aligned.m8n8.x4.shared.b16 {%0,%1,%2,%3}, [%4];" \
        : "=r"((r)[0]), "=r"((r)[1]), "=r"((r)[2]), "=r"((r)[3]) : "r"(addr))

#define MMA(d, a, bb) \
    asm volatile("mma.sync.aligned.m16n8k16.row.col.f32.bf16.bf16.f32 " \
        "{%0,%1,%2,%3},{%4,%5,%6,%7},{%8,%9},{%0,%1,%2,%3};" \
        : "+f"((d)[0]), "+f"((d)[1]), "+f"((d)[2]), "+f"((d)[3]) \
        : "r"((a)[0]), "r"((a)[1]), "r"((a)[2]), "r"((a)[3]), "r"((bb)[0]), "r"((bb)[1]))

// ------------------------------------------------------------------ pre-pass
__global__ __launch_bounds__(256) void split_prep(const float* __restrict__ f1,
                                                  const float* __restrict__ f2)
{
    __shared__ float s[32][129];
    const int bid = blockIdx.x;
    const int ib  = bid & 31;
    const int cc  = (bid >> 5) & 7;
    const int b   = (bid >> 8) & 3;
    const int arr = bid >> 10;
    const float* in = arr ? f2 : f1;
    __nv_bfloat16* o = arr ? g_B : g_A;
    const int t = threadIdx.x;

#pragma unroll
    for (int k = 0; k < 4; k++) {
        const int lin = k * 256 + t;
        const int c   = lin >> 5;
        const int x4  = lin & 31;
        const float4 v = *(const float4*)(in + ((size_t)(b*CH + cc*32 + c))*HW + ib*128 + x4*4);
        s[c][x4*4+0] = v.x; s[c][x4*4+1] = v.y; s[c][x4*4+2] = v.z; s[c][x4*4+3] = v.w;
    }
    __syncthreads();

    const int slot = t & 3;
    const size_t blk = (((size_t)(b*NCHUNK + cc))*32 + ib) * 16384;
#pragma unroll
    for (int rr = 0; rr < 2; rr++) {
        const int row = rr * 64 + (t >> 2);
        const uint32_t byte = (uint32_t)(row * 64) +
                              ((uint32_t)(slot << 4) ^ (uint32_t)(((row >> 1) & 3) << 4));
        uint32_t hp[4], lp[4];
#pragma unroll
        for (int u = 0; u < 4; u++) {
            const int c = slot*8 + u*2;
            const float v0 = s[c][row], v1 = s[c+1][row];
            const __nv_bfloat16 h0 = __float2bfloat16(v0);
            const __nv_bfloat16 h1 = __float2bfloat16(v1);
            const __nv_bfloat16 l0 = __float2bfloat16(v0 - __bfloat162float(h0));
            const __nv_bfloat16 l1 = __float2bfloat16(v1 - __bfloat162float(h1));
            hp[u] = ((uint32_t)__bfloat16_as_ushort(h1) << 16) | __bfloat16_as_ushort(h0);
            lp[u] = ((uint32_t)__bfloat16_as_ushort(l1) << 16) | __bfloat16_as_ushort(l0);
        }
        *(uint4*)((char*)o + blk        + byte) = make_uint4(hp[0], hp[1], hp[2], hp[3]);
        *(uint4*)((char*)o + blk + 8192 + byte) = make_uint4(lp[0], lp[1], lp[2], lp[3]);
    }
}

// ------------------------------------------------------------------ GEMM
// C[i,j] tile 128x128, 128 threads, bf16-3x, 3-stage pipeline, 2 CTAs/SM.
// Epilogue stores exp(x - m_split) as fp16 + per-column partial stats.
__global__ __launch_bounds__(128, 2) void corr_mma()
{
    extern __shared__ char dsm[];
    uint32_t base = smem_u32(dsm);
    base = (base + 1023) & ~1023u;
    const uint32_t mbF = base + NSTAGE * STAGEB;
    const uint32_t mbE = mbF + 24;

    const int tid  = threadIdx.x;
    const int lane = tid & 31;
    const int wid  = tid >> 5;
    const int wm   = wid >> 1;
    const int wn   = wid & 1;
    const int jt = blockIdx.x, it = blockIdx.y, b = blockIdx.z;

    if (tid == 0) {
#pragma unroll
        for (int s = 0; s < NSTAGE; s++) { mbar_init(mbF + 8*s, 1); mbar_init(mbE + 8*s, 4); }
        asm volatile("fence.proxy.async.shared::cta;" ::: "memory");
    }
    __syncthreads();

    #define ISSUE(c, s) do { \
        const size_t offA = (((size_t)(b*NCHUNK + (c)))*32 + it) * 16384; \
        const size_t offB = (((size_t)(b*NCHUNK + (c)))*32 + jt) * 16384; \
        mbar_expect(mbF + 8*(s), STAGEB); \
        bulk_g2s(base + (s)*STAGEB +     0, (const char*)g_A + offA, 16384, mbF + 8*(s)); \
        bulk_g2s(base + (s)*STAGEB + 16384, (const char*)g_B + offB, 16384, mbF + 8*(s)); \
    } while (0)

    if (tid == 0) { ISSUE(0,0); ISSUE(1,1); ISSUE(2,2); }

    float acc[4][8][4];
#pragma unroll
    for (int mt = 0; mt < 4; mt++)
#pragma unroll
        for (int nt = 0; nt < 8; nt++)
#pragma unroll
            for (int e = 0; e < 4; e++) acc[mt][nt][e] = 0.f;

    const int rA  = lane & 15;
    const int khA = (lane & 16) ? 16 : 0;
    const int rB  = (lane & 7) + ((lane & 16) ? 8 : 0);
    const int khB = (lane & 8)  ? 16 : 0;
    const uint32_t swA = (uint32_t)(((rA >> 1) & 3) << 4);
    const uint32_t swB = (uint32_t)(((rB >> 1) & 3) << 4);
    const uint32_t rowAoff = (uint32_t)((wm*64 + rA) * 64);
    const uint32_t rowBoff = (uint32_t)(16384 + (wn*64 + rB) * 64);

    for (int c = 0; c < NCHUNK; c++) {
        const int s = c % NSTAGE;
        const uint32_t par = (uint32_t)((c / NSTAGE) & 1);
        mbar_wait(mbF + 8*s, par);

        const uint32_t aAh = base + s*STAGEB + rowAoff;
        const uint32_t aAl = aAh + 8192;
        const uint32_t aBh = base + s*STAGEB + rowBoff;
        const uint32_t aBl = aBh + 8192;

#pragma unroll
        for (int kk = 0; kk < 2; kk++) {
            const uint32_t colA = ((uint32_t)(kk*32 + khA)) ^ swA;
            const uint32_t colB = ((uint32_t)(kk*32 + khB)) ^ swB;
            uint32_t ah[4][4], al[4][4], bh[4][4], bl[4][4];
#pragma unroll
            for (int mt = 0; mt < 4; mt++) {
                LDSM4(ah[mt], aAh + mt*1024 + colA);
                LDSM4(al[mt], aAl + mt*1024 + colA);
            }
#pragma unroll
            for (int np = 0; np < 4; np++) {
                LDSM4(bh[np], aBh + np*1024 + colB);
                LDSM4(bl[np], aBl + np*1024 + colB);
            }
#pragma unroll
            for (int mt = 0; mt < 4; mt++)
#pragma unroll
                for (int nt = 0; nt < 8; nt++)
                    MMA(acc[mt][nt], ah[mt], (&bh[nt >> 1][(nt & 1) * 2]));
#pragma unroll
            for (int mt = 0; mt < 4; mt++)
#pragma unroll
                for (int nt = 0; nt < 8; nt++)
                    MMA(acc[mt][nt], ah[mt], (&bl[nt >> 1][(nt & 1) * 2]));
#pragma unroll
            for (int mt = 0; mt < 4; mt++)
#pragma unroll
                for (int nt = 0; nt < 8; nt++)
                    MMA(acc[mt][nt], al[mt], (&bh[nt >> 1][(nt & 1) * 2]));
        }
        if (c < NCHUNK - NSTAGE) {
            __syncwarp();
            if (lane == 0) mbar_arrive(mbE + 8*s);
            if (tid == 0) { mbar_wait(mbE + 8*s, par); ISSUE(c + NSTAGE, s); }
        }
    }

    // ---------------- epilogue: column max -> exp -> fp16 store + partial sums
    const int g   = lane >> 2;
    const int tig = lane & 3;

    float cm[8][2], cs[8][2];
#pragma unroll
    for (int nt = 0; nt < 8; nt++)
#pragma unroll
        for (int e = 0; e < 2; e++) {
            float m = -INFINITY;
#pragma unroll
            for (int mt = 0; mt < 4; mt++) {
                m = fmaxf(m, acc[mt][nt][e]);
                m = fmaxf(m, acc[mt][nt][2 + e]);
            }
            cm[nt][e] = m;
        }
#pragma unroll
    for (int d = 4; d <= 16; d <<= 1)
#pragma unroll
        for (int nt = 0; nt < 8; nt++)
#pragma unroll
            for (int e = 0; e < 2; e++)
                cm[nt][e] = fmaxf(cm[nt][e], __shfl_xor_sync(0xffffffffu, cm[nt][e], d));

    __half* eb = g_e + (size_t)b*HW*HW + (size_t)(it*128)*HW + jt*128;
#pragma unroll
    for (int nt = 0; nt < 8; nt++) { cs[nt][0] = 0.f; cs[nt][1] = 0.f; }
#pragma unroll
    for (int mt = 0; mt < 4; mt++)
#pragma unroll
        for (int nt = 0; nt < 8; nt++) {
            const int r0 = wm*64 + mt*16 + g;
            const int cc = wn*64 + nt*8 + tig*2;
            const float e0 = __expf(acc[mt][nt][0] - cm[nt][0]);
            const float e1 = __expf(acc[mt][nt][1] - cm[nt][1]);
            const float e2 = __expf(acc[mt][nt][2] - cm[nt][0]);
            const float e3 = __expf(acc[mt][nt][3] - cm[nt][1]);
            cs[nt][0] += e0 + e2;
            cs[nt][1] += e1 + e3;
            *(__half2*)(eb + (size_t)r0     * HW + cc) = __floats2half2_rn(e0, e1);
            *(__half2*)(eb + (size_t)(r0+8) * HW + cc) = __floats2half2_rn(e2, e3);
        }
#pragma unroll
    for (int d = 4; d <= 16; d <<= 1)
#pragma unroll
        for (int nt = 0; nt < 8; nt++)
#pragma unroll
            for (int e = 0; e < 2; e++)
                cs[nt][e] += __shfl_xor_sync(0xffffffffu, cs[nt][e], d);

    if (lane < 4) {
        const int split = it*2 + wm;
#pragma unroll
        for (int nt = 0; nt < 8; nt++)
#pragma unroll
            for (int e = 0; e < 2; e++) {
                const int jg = jt*128 + wn*64 + nt*8 + lane*2 + e;
                const size_t po = ((size_t)split*BATCH + b)*HW + jg;
                g_pm[po] = cm[nt][e];
                g_ps[po] = cs[nt][e];
            }
    }
}

// ------------------------------------------------------------------ merge
// global max + sum per column, then per-split scale sc = exp(pm-m)/sum
__global__ __launch_bounds__(256) void merge_stats()
{
    const int idx = blockIdx.x * 256 + threadIdx.x;   // b*HW + j
    float m = -INFINITY;
#pragma unroll 8
    for (int s = 0; s < NSPLIT; s++)
        m = fmaxf(m, g_pm[(size_t)s * BATCH * HW + idx]);
    float sum = 0.f;
#pragma unroll 8
    for (int s = 0; s < NSPLIT; s++)
        sum += g_ps[(size_t)s * BATCH * HW + idx] *
               __expf(g_pm[(size_t)s * BATCH * HW + idx] - m);
    const float inv = 1.f / sum;
#pragma unroll 8
    for (int s = 0; s < NSPLIT; s++)
        g_sc[(size_t)s * BATCH * HW + idx] =
            __expf(g_pm[(size_t)s * BATCH * HW + idx] - m) * inv;
}

// ------------------------------------------------------------------ finalize
// out[b,i,j] = (float)g_e[b,i,j] * g_sc[i>>6][b][j]; 8 elements per thread
__global__ __launch_bounds__(256) void finalize(float* __restrict__ out)
{
    const size_t q = ((size_t)blockIdx.x * 256 + threadIdx.x) * 8;
    const int j = (int)(q & (HW - 1));
    const int i = (int)((q >> 12) & (HW - 1));
    const int b = (int)(q >> 24);

    const uint4 eraw = *(const uint4*)(g_e + q);
    const float* sc = g_sc + (size_t)(i >> 6) * BATCH * HW + (size_t)b * HW + j;
    const float4 s0 = *(const float4*)(sc);
    const float4 s1 = *(const float4*)(sc + 4);

    const float2 p0 = __half22float2(*(const __half2*)&eraw.x);
    const float2 p1 = __half22float2(*(const __half2*)&eraw.y);
    const float2 p2 = __half22float2(*(const __half2*)&eraw.z);
    const float2 p3 = __half22float2(*(const __half2*)&eraw.w);

    float4 o0, o1;
    o0.x = p0.x * s0.x;  o0.y = p0.y * s0.y;
    o0.z = p1.x * s0.z;  o0.w = p1.y * s0.w;
    o1.x = p2.x * s1.x;  o1.y = p2.y * s1.y;
    o1.z = p3.x * s1.z;  o1.w = p3.y * s1.w;

    *(float4*)(out + q)     = o0;
    *(float4*)(out + q + 4) = o1;
}

// ------------------------------------------------------------------
extern "C" void kernel_launch(void* const* d_in, const int* in_sizes, int n_in,
                              void* d_out, int out_size)
{
    const float* f1 = (const float*)d_in[0];
    const float* f2 = (const float*)d_in[1];
    float* out = (float*)d_out;

    static bool smem_set = false;
    if (!smem_set) {
        cudaFuncSetAttribute(corr_mma, cudaFuncAttributeMaxDynamicSharedMemorySize, SMEM_REQ);
        smem_set = true;
    }

    split_prep<<<2048, 256>>>(f1, f2);

    dim3 g(HW / 128, HW / 128, BATCH);           // 32 x 32 x 4
    corr_mma<<<g, 128, SMEM_REQ>>>();

    merge_stats<<<(BATCH * HW) / 256, 256>>>();

    const size_t total = (size_t)BATCH * HW * HW;
    finalize<<<(unsigned)(total / 8 / 256), 256>>>(out);
}